// round 3
// baseline (speedup 1.0000x reference)
#include <cuda_runtime.h>

#define NQ 12

__device__ __forceinline__ float ex2f(float a) {
    float r; asm("ex2.approx.f32 %0, %1;" : "=f"(r) : "f"(a)); return r;
}
__device__ __forceinline__ float rcpf(float a) {
    float r; asm("rcp.approx.f32 %0, %1;" : "=f"(r) : "f"(a)); return r;
}

// 4 lanes per row: lanes 0..2 each own one float4 (4 qubits), lane 3 pads
// the shuffle group. Pad lane computes on zeros -> ca=1, sa=0 (harmless).
__global__ __launch_bounds__(128)
void quantum_layer_kernel(const float* __restrict__ x,
                          const float* __restrict__ w,
                          float* __restrict__ out,
                          int B)
{
    __shared__ float s_cw[NQ], s_sw[NQ];
    if (threadIdx.x < NQ) {
        float s, c;
        sincosf(__ldg(&w[threadIdx.x]), &s, &c);
        s_sw[threadIdx.x] = s;
        s_cw[threadIdx.x] = c;
    }

    int t = blockIdx.x * blockDim.x + threadIdx.x;
    int b = t >> 2;          // row
    int l = t & 3;           // sub-lane within row group
    bool active = (b < B) && (l < 3);

    float4 v = make_float4(0.f, 0.f, 0.f, 0.f);
    if (active)
        v = reinterpret_cast<const float4*>(x)[(size_t)b * 3 + l];

    float xv[4] = { v.x, v.y, v.z, v.w };

    // a = 2*atan(tanh(x)):  cos a = 2u/(u^2+1), sin a = (u^2-1)/(u^2+1), u = e^{2x}
    float uu[4], u2[4], d[4];
#pragma unroll
    for (int q = 0; q < 4; q++) {
        float xc = fminf(fmaxf(xv[q], -5.0f), 5.0f);
        float u  = ex2f(xc * 2.8853900817779268f);   // 2*log2(e)
        uu[q] = u;
        u2[q] = u * u;
        d[q]  = u2[q] + 1.0f;
    }

    // One grouped reciprocal for 4 denominators (max prod ~5.5e34 < FLT_MAX).
    float d01 = d[0] * d[1];
    float d23 = d[2] * d[3];
    float ia  = rcpf(d01 * d23);
    float i01 = ia * d23;
    float i23 = ia * d01;
    float inv[4] = { i01 * d[1], i01 * d[0], i23 * d[3], i23 * d[2] };

    float ca[4], sa[4];
#pragma unroll
    for (int q = 0; q < 4; q++) {
        ca[q] = (uu[q] + uu[q]) * inv[q];
        sa[q] = (u2[q] - 1.0f)  * inv[q];
    }

    // Local prefix products of cos.
    float P0 = ca[0];
    float P1 = P0 * ca[1];
    float P2 = P1 * ca[2];
    float P3 = P2 * ca[3];

    const unsigned FULL = 0xffffffffu;
    // Cross-lane prefix: product of full-lane cos-products of lanes < l (width-4 groups).
    float p0 = __shfl_sync(FULL, P3, 0, 4);
    float p1 = __shfl_sync(FULL, P3, 1, 4);
    float prefix = (l == 0) ? 1.0f : ((l == 1) ? p0 : p0 * p1);

    // Next lane's first sin (for the boundary sa[q]*sa[q+1] term).
    float nxt = __shfl_down_sync(FULL, sa[0], 1);
    if (l == 2) nxt = 1.0f;              // q=11: S = sa[11] alone

    __syncthreads();                     // s_cw/s_sw ready; latency hidden by math above

    float S0 = sa[0] * sa[1];
    float S1 = sa[1] * sa[2];
    float S2 = sa[2] * sa[3];
    float S3 = sa[3] * nxt;

    int qb = 4 * l;
    float o0 = s_cw[qb + 0] * (prefix * P0) - s_sw[qb + 0] * S0;
    float o1 = s_cw[qb + 1] * (prefix * P1) - s_sw[qb + 1] * S1;
    float o2 = s_cw[qb + 2] * (prefix * P2) - s_sw[qb + 2] * S2;
    float o3 = s_cw[qb + 3] * (prefix * P3) - s_sw[qb + 3] * S3;

    if (active)
        reinterpret_cast<float4*>(out)[(size_t)b * 3 + l] = make_float4(o0, o1, o2, o3);
}

extern "C" void kernel_launch(void* const* d_in, const int* in_sizes, int n_in,
                              void* d_out, int out_size)
{
    const float* x = (const float*)d_in[0];   // [B, 12]
    const float* w = (const float*)d_in[1];   // [36], first 12 used
    float* out = (float*)d_out;               // [B, 12]
    int B = in_sizes[0] / NQ;

    int total = B * 4;                        // 4 lanes per row
    int threads = 128;
    int blocks = (total + threads - 1) / threads;   // 512 for B=16384
    quantum_layer_kernel<<<blocks, threads>>>(x, w, out, B);
}